// round 3
// baseline (speedup 1.0000x reference)
#include <cuda_runtime.h>
#include <cstdint>
#include <cstdio>

// Problem constants
#define Bn      16384
#define Nn      17
#define Cc      128      // CIN
#define Dd      128      // COUT
#define Kk      3
#define TB      8        // batches per CTA
#define THREADS 512
#define ROWE    (Nn*Cc)  // 2176 floats per batch

// L (k=1) and T2 (k=2) live here; k=0 is identity (handled implicitly).
__device__ float g_L[2*Nn*Nn];

// ---------------------------------------------------------------------------
// Setup kernel: Chebyshev basis from adjacency (tiny, one block)
//   L = I - D^{-1/2} A D^{-1/2};  T2 = 2 L@L - I
// ---------------------------------------------------------------------------
__global__ void cheb_kernel(const float* __restrict__ adj) {
    __shared__ float dinv[Nn];
    __shared__ float Ls[Nn*Nn];
    int t = threadIdx.x;                 // 0..288
    if (t < Nn) {
        float s = 0.f;
        #pragma unroll
        for (int m = 0; m < Nn; ++m) s += adj[t*Nn + m];
        dinv[t] = 1.0f / sqrtf(s);
    }
    __syncthreads();
    if (t < Nn*Nn) {
        int n = t / Nn, m = t % Nn;
        float l = (n == m ? 1.f : 0.f) - dinv[n] * adj[t] * dinv[m];
        Ls[t] = l;
    }
    __syncthreads();
    if (t < Nn*Nn) {
        int n = t / Nn, m = t % Nn;
        float a = 0.f;
        #pragma unroll
        for (int j = 0; j < Nn; ++j) a = fmaf(Ls[n*Nn + j], Ls[j*Nn + m], a);
        g_L[t]         = Ls[t];                          // k=1: L
        g_L[Nn*Nn + t] = 2.f * a - (n == m ? 1.f : 0.f); // k=2: T2
    }
}

// ---------------------------------------------------------------------------
// Main kernel: fused aggregation + per-order transform + bias + relu
//   out[b,n,d] = relu( sum_k sum_c u_k[b,n,c] * W_k[c,d] + bias[d] )
//   u_0 = x;  u_k = T_k @ x (over node dim, N=17)
//
// smem layout (dynamic):
//   sU2 : TB*2176 float2   (each U value duplicated {u,u} for fma.rn.f32x2)
//   sW  : 128*128 float    (current W_k)
//   sL  : 2*289   float    (L, T2)
// ---------------------------------------------------------------------------
#define SMEM_U_BYTES  (TB*ROWE*8)                 // 139264
#define SMEM_W_BYTES  (Cc*Dd*4)                   // 65536
#define SMEM_L_BYTES  (2*Nn*Nn*4)                 // 2312
#define SMEM_TOTAL    (SMEM_U_BYTES + SMEM_W_BYTES + SMEM_L_BYTES)

__global__ void __launch_bounds__(THREADS, 1)
graphcheb_main(const float* __restrict__ x, const float* __restrict__ w,
               const float* __restrict__ bias, float* __restrict__ out) {
    extern __shared__ char smem[];
    float2* sU2 = (float2*)smem;                               // TB*2176 entries
    float*  sW  = (float*)(smem + SMEM_U_BYTES);               // 16384 floats
    float*  sL  = (float*)(smem + SMEM_U_BYTES + SMEM_W_BYTES);

    const int tid = threadIdx.x;
    const int b0  = blockIdx.x * TB;
    const int b   = tid >> 6;          // 0..7  (local batch)
    const int dp  = tid & 63;          // d-pair index: covers d = 2*dp, 2*dp+1
    const float2* uB = sU2 + b * ROWE;
    const float* xt  = x + (size_t)b0 * ROWE;   // contiguous 8-batch tile

    // --- prologue: L matrices, k=0 U (= dup(x)), W_0 ---
    for (int i = tid; i < 2*Nn*Nn; i += THREADS) sL[i] = g_L[i];
    for (int i = tid; i < TB*ROWE; i += THREADS) {
        float v = xt[i];
        sU2[i] = make_float2(v, v);
    }
    {
        const float4* wg = (const float4*)w;
        float4* sw4 = (float4*)sW;
        for (int i = tid; i < (Cc*Dd)/4; i += THREADS) sw4[i] = wg[i];
    }
    __syncthreads();

    // packed f32x2 accumulators: acc[n] = {out[b,n,2dp], out[b,n,2dp+1]}
    uint64_t acc[Nn];
    #pragma unroll
    for (int n = 0; n < Nn; ++n) acc[n] = 0ull;

    #pragma unroll 1
    for (int k = 0; k < Kk; ++k) {
        // ---- GEMM: acc[n] += u[b,n,c] * W_k[c, 2dp..2dp+1] over c ----
        #pragma unroll 2
        for (int c = 0; c < Cc; ++c) {
            uint64_t wv = *(const uint64_t*)(sW + c*Dd + 2*dp);   // LDS.64, lane-consecutive
            const float2* up = uB + c;
            #pragma unroll
            for (int n = 0; n < Nn; ++n) {
                uint64_t uv = *(const uint64_t*)(up + (size_t)n*Cc); // LDS.64 broadcast {u,u}
                asm("fma.rn.f32x2 %0, %1, %2, %0;" : "+l"(acc[n]) : "l"(uv), "l"(wv));
            }
        }
        if (k == Kk - 1) break;
        __syncthreads();   // everyone done with sU2/sW for this k

        // ---- stage k+1: load W_{k+1}; aggregate U_{k+1} from global x ----
        {
            const float4* wg = (const float4*)(w + (size_t)(k+1)*Cc*Dd);
            float4* sw4 = (float4*)sW;
            for (int i = tid; i < (Cc*Dd)/4; i += THREADS) sw4[i] = wg[i];
        }
        const float* Lr = sL + k*Nn*Nn;   // (k+1)-th basis stored at slot k
        #pragma unroll 1
        for (int s = 0; s < (TB*Cc)/THREADS; ++s) {   // 2 points (b,c) per thread
            int p  = tid + s*THREADS;                 // 0..1023
            int bb = p >> 7, c = p & 127;
            const float* xg = xt + bb*ROWE + c;
            float xr[Nn];
            #pragma unroll
            for (int m = 0; m < Nn; ++m) xr[m] = xg[m*Cc];   // coalesced LDG
            float2* uo = sU2 + bb*ROWE + c;
            #pragma unroll
            for (int n = 0; n < Nn; ++n) {
                float u = 0.f;
                #pragma unroll
                for (int m = 0; m < Nn; ++m) u = fmaf(Lr[n*Nn + m], xr[m], u);
                uo[(size_t)n*Cc] = make_float2(u, u);
            }
        }
        __syncthreads();
    }

    // ---- epilogue: bias + relu, coalesced float2 stores ----
    float2 bv = *(const float2*)(bias + 2*dp);
    float* og = out + (size_t)(b0 + b) * ROWE + 2*dp;
    #pragma unroll
    for (int n = 0; n < Nn; ++n) {
        float2 a = *reinterpret_cast<float2*>(&acc[n]);
        a.x = fmaxf(a.x + bv.x, 0.f);
        a.y = fmaxf(a.y + bv.y, 0.f);
        *(float2*)(og + (size_t)n*Cc) = a;
    }
}

// ---------------------------------------------------------------------------
extern "C" void kernel_launch(void* const* d_in, const int* in_sizes, int n_in,
                              void* d_out, int out_size) {
    const float* x    = (const float*)d_in[0];   // [16384,17,128]
    const float* adj  = (const float*)d_in[1];   // [17,17]
    const float* w    = (const float*)d_in[2];   // [3,1,128,128]
    const float* bias = (const float*)d_in[3];   // [1,1,128]
    float* out = (float*)d_out;                  // [16384,17,128]

    // idempotent, executes immediately (not a stream op) -> capture-safe
    cudaFuncSetAttribute(graphcheb_main,
                         cudaFuncAttributeMaxDynamicSharedMemorySize, SMEM_TOTAL);

    cheb_kernel<<<1, Nn*Nn>>>(adj);
    graphcheb_main<<<Bn/TB, THREADS, SMEM_TOTAL>>>(x, w, bias, out);
}